// round 16
// baseline (speedup 1.0000x reference)
#include <cuda_runtime.h>
#include <math.h>

#define Bn   4
#define Hn   192
#define Wn   192
#define Qn   160
#define En   96
#define Mn   96
#define HW   (Hn*Wn)          /* 36864 */
#define NPIX (Bn*HW)          /* 147456 */

#define DBLK 576              /* blocks per batch: 576*8 warps*8 px = 36864 */
#define NBLK (DBLK*Bn)        /* 2304 total blocks */
#define SMALLB 64             /* blocks (b==0, bx<64) doing the small losses */

// Partial-sum scratch. g_pd/g_po fully overwritten every launch by all blocks;
// g_ps overwritten by the same 64 blocks every launch. Counter reset by the
// last block each launch -> graph replays see 0 again. Deterministic: the
// final fold is executed by exactly one block in a fixed sequential order.
__device__ double g_pd[Bn][DBLK][2];   // dice: [0]=num, [1]=sum_true
__device__ double g_po[Bn][DBLK];      // occupancy partials
__device__ double g_ps[SMALLB][3];     // class, bce, nll
__device__ unsigned int g_cnt = 0;

__device__ __forceinline__ float softplusf(float x) {
    return fmaxf(x, 0.0f) + log1pf(__expf(-fabsf(x)));
}

__device__ __forceinline__ double warp_red(double v) {
    #pragma unroll
    for (int o = 16; o; o >>= 1) v += __shfl_xor_sync(~0u, v, o);
    return v;
}

// Valid result on tid 0 only. Safe to call back-to-back (internal syncs).
__device__ double block_red0(double v, double* sm8) {
    int warp = threadIdx.x >> 5, lane = threadIdx.x & 31;
    v = warp_red(v);
    if (lane == 0) sm8[warp] = v;
    __syncthreads();
    double r = 0.0;
    if (threadIdx.x == 0) {
        #pragma unroll
        for (int w = 0; w < 8; w++) r += sm8[w];
    }
    __syncthreads();
    return r;
}

__global__ __launch_bounds__(256) void fused_kernel(
    const float*  __restrict__ iel,
    const float*  __restrict__ tseg,
    const float*  __restrict__ binl,
    const float*  __restrict__ porl,
    const float*  __restrict__ inc,
    const float*  __restrict__ pos,
    const float*  __restrict__ chl,
    const float4* __restrict__ occl,
    const int*    __restrict__ occt,
    const int*    __restrict__ mq,
    const int*    __restrict__ me,
    float*        __restrict__ out)
{
    __shared__ int    s_pair[Qn];        // inverse map: q-channel -> e-channel (-1 if unmatched)
    __shared__ float4 s_t4[8][24];       // per-warp staged true row (96 floats)
    __shared__ double sm8[8];
    __shared__ double s_num[8], s_tv[8];
    __shared__ unsigned int s_last;

    const int b = blockIdx.y, bx = blockIdx.x;
    const int tid = threadIdx.x, warp = tid >> 5, lane = tid & 31;

    // ---- build per-batch inverse pairing map ----
    if (tid < Qn) s_pair[tid] = -1;
    __syncthreads();
    if (tid < Mn) s_pair[mq[b * Mn + tid]] = me[b * Mn + tid];
    __syncthreads();

    // hoist this lane's pairing entries to registers (conflict-free LDS: bank==lane)
    int prr[8];
    #pragma unroll
    for (int j = 0; j < 4; j++) prr[j] = s_pair[4 * lane + j];
    #pragma unroll
    for (int j = 0; j < 4; j++) prr[4 + j] = (lane < 8) ? s_pair[128 + 4 * lane + j] : -1;

    // ================= dice main pass (coalesced loads + SMEM gather) =======
    const float* porB = porl + (size_t)b * HW * Qn;
    const float* tB   = tseg + (size_t)b * HW * En;
    const float* s_tw = (const float*)s_t4[warp];

    double num = 0.0, tvs = 0.0;
    #pragma unroll 1
    for (int it = 0; it < 8; it++) {
        const int pix = (bx * 8 + warp) + it * (DBLK * 8);
        const float4* xp = (const float4*)(porB + (size_t)pix * Qn);
        const float4* tp = (const float4*)(tB   + (size_t)pix * En);

        float4 xa = __ldg(xp + lane);                              // q-channels 4*lane..+3
        float4 xb = make_float4(0.f, 0.f, 0.f, 0.f);
        if (lane < 8) xb = __ldg(xp + 32 + lane);                  // q-channels 128+4*lane..+3
        float4 t4 = make_float4(0.f, 0.f, 0.f, 0.f);
        if (lane < 24) { t4 = __ldg(tp + lane); s_t4[warp][lane] = t4; }
        float tvloc = t4.x + t4.y + t4.z + t4.w;
        __syncwarp();

        float xs[8] = {xa.x, xa.y, xa.z, xa.w, xb.x, xb.y, xb.z, xb.w};
        float mx = -3.4e38f;
        #pragma unroll
        for (int j = 0; j < 8; j++) if (prr[j] >= 0) mx = fmaxf(mx, xs[j]);
        #pragma unroll
        for (int o = 16; o; o >>= 1) mx = fmaxf(mx, __shfl_xor_sync(~0u, mx, o));

        float se = 0.f, dt = 0.f;
        #pragma unroll
        for (int j = 0; j < 8; j++) if (prr[j] >= 0) {
            float ex = __expf(xs[j] - mx);
            se += ex;
            dt += s_tw[prr[j]] * ex;
        }
        #pragma unroll
        for (int o = 16; o; o >>= 1) {
            se    += __shfl_xor_sync(~0u, se, o);
            dt    += __shfl_xor_sync(~0u, dt, o);
            tvloc += __shfl_xor_sync(~0u, tvloc, o);
        }
        num += (double)(2.0f * dt / se);
        tvs += (double)tvloc;
        __syncwarp();   // protect s_t4 reuse next iteration
    }
    if (lane == 0) { s_num[warp] = num; s_tv[warp] = tvs; }

    // ================= occupancy CE (this block's slice of batch b) =========
    double occ_acc = 0.0;
    {
        int oi = bx * 256 + tid;
        if (oi < HW) {
            int gi = b * HW + oi;
            float4 v = __ldg(occl + gi);
            int t = __ldg(occt + gi);
            float m4 = fmaxf(fmaxf(v.x, v.y), fmaxf(v.z, v.w));
            float sum = __expf(v.x - m4) + __expf(v.y - m4)
                      + __expf(v.z - m4) + __expf(v.w - m4);
            float xt = (t == 0) ? v.x : (t == 1) ? v.y : (t == 2) ? v.z : v.w;
            occ_acc = (double)(xt - m4 - logf(sum));
        }
    }

    // ================= small losses (64 blocks of batch-plane 0) ============
    double a_class = 0.0, a_bce = 0.0, a_nll = 0.0;
    if (b == 0 && bx < SMALLB) {
        const int NCLASS = Bn * Qn;        // 640
        const int NNLL   = Bn * Mn;        // 384
        const int NBCE   = Bn * Mn * 49;   // 18816
        const int total  = NCLASS + NNLL + NBCE;
        for (int i = bx * 256 + tid; i < total; i += SMALLB * 256) {
            if (i < NCLASS) {
                int bb = i / Qn, q = i % Qn;
                float x = iel[i];
                bool lab = false;
                const int* mqb = mq + bb * Mn;
                #pragma unroll 8
                for (int m = 0; m < Mn; m++) if (mqb[m] == q) { lab = true; break; }
                float z = lab ? 1.0f : 0.0f;
                float w = lab ? 1.0f : 0.1f;
                a_class += (double)(w * (softplusf(x) - x * z));
            } else if (i < NCLASS + NNLL) {
                int j = i - NCLASS;
                int bb = j / Mn, m = j % Mn;
                int e = me[bb * Mn + m];
                int q = mq[bb * Mn + m];
                float p0 = inc[(bb * En + e) * 2 + 0];
                float p1 = inc[(bb * En + e) * 2 + 1];
                float c0 = pos[(bb * Qn + q) * 2 + 0];
                float c1 = pos[(bb * Qn + q) * 2 + 1];
                float l00 = chl[(bb * Qn + q) * 4 + 0];
                float l10 = chl[(bb * Qn + q) * 4 + 2];
                float l11 = chl[(bb * Qn + q) * 4 + 3];
                float z0 = (p0 - c0) / l00;
                float z1 = ((p1 - c1) - l10 * z0) / l11;
                float nll = 0.5f * (z0 * z0 + z1 * z1)
                          + 1.8378770664093453f + logf(l00) + logf(l11);
                if (isinf(nll)) nll = 1e7f;
                a_nll += (double)nll;
            } else {
                int k = i - NCLASS - NNLL;
                int bb = k / (Mn * 49);
                int r = k % (Mn * 49);
                int m = r / 49;
                int w49 = r % 49;
                int wy = w49 / 7 - 3;
                int wx = w49 % 7 - 3;
                int e = me[bb * Mn + m];
                int q = mq[bb * Mn + m];
                float p0 = inc[(bb * En + e) * 2 + 0];
                float p1 = inc[(bb * En + e) * 2 + 1];
                int row = (int)floorf(p0) + wy;
                int col = (int)floorf(p1) + wx;
                size_t pixbase = ((size_t)(bb * Hn + row) * Wn + col);
                float tv = tseg[pixbase * En + e];
                float lg = binl[pixbase * Qn + q];
                a_bce += (double)(softplusf(lg) - lg * tv);
            }
        }
    }
    __syncthreads();

    // ================= per-block reductions + publish ======================
    double occ_r = block_red0(occ_acc, sm8);
    double cl_r  = block_red0(a_class, sm8);
    double bce_r = block_red0(a_bce,  sm8);
    double nll_r = block_red0(a_nll,  sm8);

    if (tid == 0) {
        double n = 0.0, t = 0.0;
        #pragma unroll
        for (int w = 0; w < 8; w++) { n += s_num[w]; t += s_tv[w]; }
        g_pd[b][bx][0] = n;
        g_pd[b][bx][1] = t;
        g_po[b][bx]    = occ_r;
        if (b == 0 && bx < SMALLB) {
            g_ps[bx][0] = cl_r; g_ps[bx][1] = bce_r; g_ps[bx][2] = nll_r;
        }
        __threadfence();
        s_last = atomicAdd(&g_cnt, 1u);
    }
    __syncthreads();
    if (s_last != NBLK - 1) return;

    // ================= final fold (last block only) ========================
    double v, dice = 0.0;
    for (int bb = 0; bb < Bn; bb++) {
        v = 0.0; for (int i = tid; i < DBLK; i += 256) v += g_pd[bb][i][0];
        double nb = block_red0(v, sm8);
        v = 0.0; for (int i = tid; i < DBLK; i += 256) v += g_pd[bb][i][1];
        double tb = block_red0(v, sm8);
        if (tid == 0) dice += 1.0 - (nb + 1.0) / (tb + (double)HW + 1.0);
    }
    v = 0.0;
    for (int i = tid; i < NBLK; i += 256) v += g_po[i / DBLK][i % DBLK];
    double occ_s = block_red0(v, sm8);
    v = (tid < SMALLB) ? g_ps[tid][0] : 0.0;
    double cls = block_red0(v, sm8);
    v = (tid < SMALLB) ? g_ps[tid][1] : 0.0;
    double bces = block_red0(v, sm8);
    v = (tid < SMALLB) ? g_ps[tid][2] : 0.0;
    double nlls = block_red0(v, sm8);

    if (tid == 0) {
        double class_loss = cls  / (double)(Bn * Qn);
        double bce_loss   = bces / (double)(Bn * Mn * 49);
        double nll_loss   = nlls / (double)(Bn * Mn);
        double occ_loss   = -occ_s / (double)NPIX;
        double dice_loss  = dice / (double)Bn;
        out[0] = (float)(class_loss + bce_loss + dice_loss + nll_loss + occ_loss);
        g_cnt = 0;   // reset for next graph replay
    }
}

extern "C" void kernel_launch(void* const* d_in, const int* in_sizes, int n_in,
                              void* d_out, int out_size)
{
    const float* iel  = (const float*)d_in[0];
    const float* tseg = (const float*)d_in[1];
    const float* binl = (const float*)d_in[2];
    const float* porl = (const float*)d_in[3];
    const float* inc  = (const float*)d_in[4];
    const float* pos  = (const float*)d_in[5];
    const float* chl  = (const float*)d_in[6];
    const float* occl = (const float*)d_in[7];
    const int*   occt = (const int*)d_in[8];
    const int*   mq   = (const int*)d_in[9];
    const int*   me   = (const int*)d_in[10];

    fused_kernel<<<dim3(DBLK, Bn), 256>>>(
        iel, tseg, binl, porl, inc, pos, chl,
        (const float4*)occl, occt, mq, me, (float*)d_out);
}

// round 17
// speedup vs baseline: 1.4003x; 1.4003x over previous
#include <cuda_runtime.h>
#include <math.h>

#define Bn   4
#define Hn   192
#define Wn   192
#define Qn   160
#define En   96
#define Mn   96
#define HW   (Hn*Wn)          /* 36864 */
#define NPIX (Bn*HW)          /* 147456 */

#define DBLK 576              /* blocks per batch: 576*8 warps*8 px = 36864 */
#define NBLK (DBLK*Bn)        /* 2304 total blocks */
#define SMALLB 64             /* blocks (b==0, bx<64) doing the small losses */

// Partial-sum scratch, fully overwritten each launch. Counter reset by the
// last block each launch -> graph replays see 0 again. Deterministic: the
// final fold runs in exactly one block with a fixed reduction order.
__device__ double g_pd[Bn][DBLK][2];   // dice: [0]=num, [1]=sum_true
__device__ double g_po[Bn][DBLK];      // occupancy partials
__device__ double g_ps[SMALLB][3];     // class, bce, nll
__device__ unsigned int g_cnt = 0;

__device__ __forceinline__ float softplusf(float x) {
    return fmaxf(x, 0.0f) + log1pf(__expf(-fabsf(x)));
}

__device__ __forceinline__ double warp_red(double v) {
    #pragma unroll
    for (int o = 16; o; o >>= 1) v += __shfl_xor_sync(~0u, v, o);
    return v;
}

// Valid result on tid 0 only. Safe to call back-to-back (internal syncs).
__device__ double block_red0(double v, double* sm8) {
    int warp = threadIdx.x >> 5, lane = threadIdx.x & 31;
    v = warp_red(v);
    if (lane == 0) sm8[warp] = v;
    __syncthreads();
    double r = 0.0;
    if (threadIdx.x == 0) {
        #pragma unroll
        for (int w = 0; w < 8; w++) r += sm8[w];
    }
    __syncthreads();
    return r;
}

__global__ __launch_bounds__(256) void fused_kernel(
    const float*  __restrict__ iel,
    const float*  __restrict__ tseg,
    const float*  __restrict__ binl,
    const float*  __restrict__ porl,
    const float*  __restrict__ inc,
    const float*  __restrict__ pos,
    const float*  __restrict__ chl,
    const float4* __restrict__ occl,
    const int*    __restrict__ occt,
    const int*    __restrict__ mq,
    const int*    __restrict__ me,
    float*        __restrict__ out)
{
    __shared__ int    s_qe[En];          // e-channel -> matched q-channel
    __shared__ double sm8[8];
    __shared__ double s_num[8], s_tv[8];
    __shared__ unsigned int s_last;

    const int b = blockIdx.y, bx = blockIdx.x;
    const int tid = threadIdx.x, warp = tid >> 5, lane = tid & 31;

    // matched_e is a full permutation of [0,En): build e -> q map
    if (tid < Mn) s_qe[me[b * Mn + tid]] = mq[b * Mn + tid];
    __syncthreads();

    // this lane handles e-channels lane, lane+32, lane+64
    const int m0 = s_qe[lane], m1 = s_qe[lane + 32], m2 = s_qe[lane + 64];

    // ================= dice main pass =======================================
    // t loads: dense coalesced (1 wavefront each); x loads: gathered by q.
    // Full unroll -> ~48 loads in flight per warp (MLP).
    const float* porB = porl + (size_t)b * HW * Qn;
    const float* tB   = tseg + (size_t)b * HW * En;

    double num = 0.0, tvs = 0.0;
    #pragma unroll
    for (int it = 0; it < 8; it++) {
        const int pix = (bx * 8 + warp) + it * (DBLK * 8);
        const float* pp = porB + (size_t)pix * Qn;
        const float* tp = tB   + (size_t)pix * En;

        float t0 = __ldg(tp + lane);
        float t1 = __ldg(tp + lane + 32);
        float t2 = __ldg(tp + lane + 64);
        float x0 = __ldg(pp + m0);
        float x1 = __ldg(pp + m1);
        float x2 = __ldg(pp + m2);

        float mx = fmaxf(fmaxf(x0, x1), x2);
        #pragma unroll
        for (int o = 16; o; o >>= 1) mx = fmaxf(mx, __shfl_xor_sync(~0u, mx, o));

        float ex0 = __expf(x0 - mx), ex1 = __expf(x1 - mx), ex2 = __expf(x2 - mx);
        float se = ex0 + ex1 + ex2;
        float dt = t0 * ex0 + t1 * ex1 + t2 * ex2;
        float tv = t0 + t1 + t2;
        #pragma unroll
        for (int o = 16; o; o >>= 1) {
            se += __shfl_xor_sync(~0u, se, o);
            dt += __shfl_xor_sync(~0u, dt, o);
            tv += __shfl_xor_sync(~0u, tv, o);
        }
        num += (double)(2.0f * dt / se);
        tvs += (double)tv;
    }
    if (lane == 0) { s_num[warp] = num; s_tv[warp] = tvs; }

    // ================= occupancy CE (this block's slice of batch b) =========
    double occ_acc = 0.0;
    {
        int oi = bx * 256 + tid;
        if (oi < HW) {
            int gi = b * HW + oi;
            float4 v = __ldg(occl + gi);
            int t = __ldg(occt + gi);
            float m4 = fmaxf(fmaxf(v.x, v.y), fmaxf(v.z, v.w));
            float sum = __expf(v.x - m4) + __expf(v.y - m4)
                      + __expf(v.z - m4) + __expf(v.w - m4);
            float xt = (t == 0) ? v.x : (t == 1) ? v.y : (t == 2) ? v.z : v.w;
            occ_acc = (double)(xt - m4 - logf(sum));
        }
    }

    // ================= small losses (64 blocks of batch-plane 0) ============
    double a_class = 0.0, a_bce = 0.0, a_nll = 0.0;
    if (b == 0 && bx < SMALLB) {
        const int NCLASS = Bn * Qn;        // 640
        const int NNLL   = Bn * Mn;        // 384
        const int NBCE   = Bn * Mn * 49;   // 18816
        const int total  = NCLASS + NNLL + NBCE;
        for (int i = bx * 256 + tid; i < total; i += SMALLB * 256) {
            if (i < NCLASS) {
                int bb = i / Qn, q = i % Qn;
                float x = iel[i];
                bool lab = false;
                const int* mqb = mq + bb * Mn;
                #pragma unroll 8
                for (int m = 0; m < Mn; m++) if (mqb[m] == q) { lab = true; break; }
                float z = lab ? 1.0f : 0.0f;
                float w = lab ? 1.0f : 0.1f;
                a_class += (double)(w * (softplusf(x) - x * z));
            } else if (i < NCLASS + NNLL) {
                int j = i - NCLASS;
                int bb = j / Mn, m = j % Mn;
                int e = me[bb * Mn + m];
                int q = mq[bb * Mn + m];
                float p0 = inc[(bb * En + e) * 2 + 0];
                float p1 = inc[(bb * En + e) * 2 + 1];
                float c0 = pos[(bb * Qn + q) * 2 + 0];
                float c1 = pos[(bb * Qn + q) * 2 + 1];
                float l00 = chl[(bb * Qn + q) * 4 + 0];
                float l10 = chl[(bb * Qn + q) * 4 + 2];
                float l11 = chl[(bb * Qn + q) * 4 + 3];
                float z0 = (p0 - c0) / l00;
                float z1 = ((p1 - c1) - l10 * z0) / l11;
                float nll = 0.5f * (z0 * z0 + z1 * z1)
                          + 1.8378770664093453f + logf(l00) + logf(l11);
                if (isinf(nll)) nll = 1e7f;
                a_nll += (double)nll;
            } else {
                int k = i - NCLASS - NNLL;
                int bb = k / (Mn * 49);
                int r = k % (Mn * 49);
                int m = r / 49;
                int w49 = r % 49;
                int wy = w49 / 7 - 3;
                int wx = w49 % 7 - 3;
                int e = me[bb * Mn + m];
                int q = mq[bb * Mn + m];
                float p0 = inc[(bb * En + e) * 2 + 0];
                float p1 = inc[(bb * En + e) * 2 + 1];
                int row = (int)floorf(p0) + wy;
                int col = (int)floorf(p1) + wx;
                size_t pixbase = ((size_t)(bb * Hn + row) * Wn + col);
                float tv = tseg[pixbase * En + e];
                float lg = binl[pixbase * Qn + q];
                a_bce += (double)(softplusf(lg) - lg * tv);
            }
        }
    }
    __syncthreads();

    // ================= per-block reductions + publish ======================
    double occ_r = block_red0(occ_acc, sm8);
    double cl_r  = 0.0, bce_r = 0.0, nll_r = 0.0;
    if (b == 0 && bx < SMALLB) {       // uniform across block (b, bx uniform)
        cl_r  = block_red0(a_class, sm8);
        bce_r = block_red0(a_bce,  sm8);
        nll_r = block_red0(a_nll,  sm8);
    }

    if (tid == 0) {
        double n = 0.0, t = 0.0;
        #pragma unroll
        for (int w = 0; w < 8; w++) { n += s_num[w]; t += s_tv[w]; }
        g_pd[b][bx][0] = n;
        g_pd[b][bx][1] = t;
        g_po[b][bx]    = occ_r;
        if (b == 0 && bx < SMALLB) {
            g_ps[bx][0] = cl_r; g_ps[bx][1] = bce_r; g_ps[bx][2] = nll_r;
        }
        __threadfence();
        s_last = atomicAdd(&g_cnt, 1u);
    }
    __syncthreads();
    if (s_last != NBLK - 1) return;

    // ================= final fold (last block only) ========================
    double v, dice = 0.0;
    for (int bb = 0; bb < Bn; bb++) {
        v = 0.0; for (int i = tid; i < DBLK; i += 256) v += g_pd[bb][i][0];
        double nb = block_red0(v, sm8);
        v = 0.0; for (int i = tid; i < DBLK; i += 256) v += g_pd[bb][i][1];
        double tb = block_red0(v, sm8);
        if (tid == 0) dice += 1.0 - (nb + 1.0) / (tb + (double)HW + 1.0);
    }
    v = 0.0;
    for (int i = tid; i < NBLK; i += 256) v += g_po[i / DBLK][i % DBLK];
    double occ_s = block_red0(v, sm8);
    v = (tid < SMALLB) ? g_ps[tid][0] : 0.0;
    double cls = block_red0(v, sm8);
    v = (tid < SMALLB) ? g_ps[tid][1] : 0.0;
    double bces = block_red0(v, sm8);
    v = (tid < SMALLB) ? g_ps[tid][2] : 0.0;
    double nlls = block_red0(v, sm8);

    if (tid == 0) {
        double class_loss = cls  / (double)(Bn * Qn);
        double bce_loss   = bces / (double)(Bn * Mn * 49);
        double nll_loss   = nlls / (double)(Bn * Mn);
        double occ_loss   = -occ_s / (double)NPIX;
        double dice_loss  = dice / (double)Bn;
        out[0] = (float)(class_loss + bce_loss + dice_loss + nll_loss + occ_loss);
        g_cnt = 0;   // reset for next graph replay
    }
}

extern "C" void kernel_launch(void* const* d_in, const int* in_sizes, int n_in,
                              void* d_out, int out_size)
{
    const float* iel  = (const float*)d_in[0];
    const float* tseg = (const float*)d_in[1];
    const float* binl = (const float*)d_in[2];
    const float* porl = (const float*)d_in[3];
    const float* inc  = (const float*)d_in[4];
    const float* pos  = (const float*)d_in[5];
    const float* chl  = (const float*)d_in[6];
    const float* occl = (const float*)d_in[7];
    const int*   occt = (const int*)d_in[8];
    const int*   mq   = (const int*)d_in[9];
    const int*   me   = (const int*)d_in[10];

    fused_kernel<<<dim3(DBLK, Bn), 256>>>(
        iel, tseg, binl, porl, inc, pos, chl,
        (const float4*)occl, occt, mq, me, (float*)d_out);
}